// round 1
// baseline (speedup 1.0000x reference)
#include <cuda_runtime.h>
#include <math.h>
#include <stdint.h>

// ---------------------------------------------------------------------------
// Problem constants (B fixed at 8192 by setup_inputs; buffers sized for it)
// ---------------------------------------------------------------------------
#define MAXB 8192

__device__ float g_conv1[(size_t)MAXB * 64 * 400];   // [B,64,20,20]
__device__ float g_pool1[(size_t)MAXB * 64 * 100];   // [B,64,10,10]
__device__ float g_conv2[(size_t)MAXB * 128 * 100];  // [B,128,10,10]
__device__ float g_pool2[(size_t)MAXB * 128 * 25];   // [B,128,5,5]
__device__ float g_conv3[(size_t)MAXB * 256 * 25];   // [B,256,5,5]
__device__ float g_feat [(size_t)25 * MAXB * 256];   // [25,B,256]  (node-major feats)
__device__ float g_preds[(size_t)25 * MAXB * 10];    // [25,B,10]   stage-1 softmax
__device__ float g_scale[704];                        // folded BN scale (64+128+256+256)
__device__ float g_bias[704];                         // folded BN bias

// ---------------------------------------------------------------------------
// BN fold: scale = g/sqrt(v+eps); bias = (b-m)*scale + be
// ---------------------------------------------------------------------------
__global__ void bn_prep(const float* __restrict__ b, const float* __restrict__ g,
                        const float* __restrict__ be, const float* __restrict__ m,
                        const float* __restrict__ v, int C, int off)
{
    int c = blockIdx.x * blockDim.x + threadIdx.x;
    if (c < C) {
        float sc = g[c] / sqrtf(v[c] + 1e-5f);
        g_scale[off + c] = sc;
        g_bias[off + c]  = (b[c] - m[c]) * sc + be[c];
    }
}

// ---------------------------------------------------------------------------
// Generic 3x3 conv (pad 1) + folded BN + ReLU.
// Block = (5x5 output tile, image). Thread = output channel.
// Input chunk (ICCHUNK channels x 7x7 halo) staged to smem (broadcast reads),
// weights staged transposed with odd stride (conflict-free per-oc reads).
// Per ic: 49 input values pulled into registers, 225 FMAs -> ~1 B/FMA smem.
// FEATOUT=true writes [node][b][oc] layout for the MLP stage (HW must be 5).
// ---------------------------------------------------------------------------
template<int IC, int OC, int ICCHUNK, int HW, int NTHREADS, bool FEATOUT>
__launch_bounds__(NTHREADS, 2)
__global__ void conv_bn_relu_kernel(const float* __restrict__ in,
                                    const float* __restrict__ wt,
                                    const float* __restrict__ ks,
                                    const float* __restrict__ kb,
                                    float* __restrict__ out, int B)
{
    constexpr int TILES = HW / 5;
    constexpr int CH9 = ICCHUNK * 9;
    constexpr int WSTRIDE = (CH9 % 2 == 0) ? (CH9 + 1) : CH9;

    extern __shared__ float dyn[];
    float* in_s = dyn;                      // ICCHUNK*49
    float* w_s  = dyn + ICCHUNK * 49;       // OC*WSTRIDE

    const int tile = blockIdx.x;
    const int b    = blockIdx.y;
    const int ty0  = (tile / TILES) * 5;
    const int tx0  = (tile % TILES) * 5;
    const int oc   = threadIdx.x;           // NTHREADS == OC

    float acc[25];
    #pragma unroll
    for (int p = 0; p < 25; p++) acc[p] = 0.f;

    for (int ic0 = 0; ic0 < IC; ic0 += ICCHUNK) {
        __syncthreads();
        // input chunk with zero-padded 7x7 halo
        for (int idx = threadIdx.x; idx < ICCHUNK * 49; idx += NTHREADS) {
            int i = idx / 49, r = idx % 49;
            int y = ty0 - 1 + r / 7;
            int x = tx0 - 1 + r % 7;
            float v = 0.f;
            if (y >= 0 && y < HW && x >= 0 && x < HW)
                v = in[(((size_t)b * IC + ic0 + i) * HW + y) * HW + x];
            in_s[idx] = v;
        }
        // weights: w_s[oc*WSTRIDE + (ic_local*9+k)]  (contiguous runs of CH9 in gmem)
        for (int idx = threadIdx.x; idx < OC * CH9; idx += NTHREADS) {
            int o = idx / CH9, r = idx % CH9;
            w_s[o * WSTRIDE + r] = wt[((size_t)o * IC + ic0) * 9 + r];
        }
        __syncthreads();

        #pragma unroll 1
        for (int i = 0; i < ICCHUNK; i++) {
            float inv[49];
            #pragma unroll
            for (int v = 0; v < 49; v++) inv[v] = in_s[i * 49 + v];
            const float* wp = &w_s[oc * WSTRIDE + i * 9];
            #pragma unroll
            for (int k = 0; k < 9; k++) {
                float wv = wp[k];
                int ky = k / 3, kx = k % 3;
                #pragma unroll
                for (int p = 0; p < 25; p++) {
                    int py = p / 5, px = p % 5;
                    acc[p] = fmaf(wv, inv[(py + ky) * 7 + (px + kx)], acc[p]);
                }
            }
        }
    }

    float s  = ks[oc];
    float bs = kb[oc];
    #pragma unroll
    for (int p = 0; p < 25; p++) {
        float y = fmaxf(fmaf(acc[p], s, bs), 0.f);
        int py = p / 5, px = p % 5;
        if (FEATOUT) {
            // node = p (HW==5, single tile); layout [node][b][oc]
            out[((size_t)p * B + b) * OC + oc] = y;
        } else {
            out[(((size_t)b * OC + oc) * HW + ty0 + py) * HW + tx0 + px] = y;
        }
    }
}

// ---------------------------------------------------------------------------
// MaxPool2d(kernel=3, stride=2, padding=1): HxH -> (H/2)x(H/2)
// ---------------------------------------------------------------------------
__global__ void maxpool_kernel(const float* __restrict__ in, float* __restrict__ out,
                               int B, int C, int H)
{
    int OH = H / 2;
    size_t total = (size_t)B * C * OH * OH;
    size_t idx = (size_t)blockIdx.x * blockDim.x + threadIdx.x;
    if (idx >= total) return;
    int ox = idx % OH;
    int oy = (idx / OH) % OH;
    size_t bc = idx / ((size_t)OH * OH);
    const float* p = in + bc * H * H;
    float m = -3.4e38f;
    #pragma unroll
    for (int dy = -1; dy <= 1; dy++) {
        int iy = 2 * oy + dy;
        if (iy < 0 || iy >= H) continue;
        #pragma unroll
        for (int dx = -1; dx <= 1; dx++) {
            int ix = 2 * ox + dx;
            if (ix < 0 || ix >= H) continue;
            m = fmaxf(m, p[iy * H + ix]);
        }
    }
    out[idx] = m;
}

// ---------------------------------------------------------------------------
// Neighbor table (replicates reference ordering exactly, w=h=5)
// ---------------------------------------------------------------------------
__device__ __forceinline__ int nei_of(int i, int j)
{
    int n[8]; int cnt = 0;
    if (i - 5 >= 0)                          n[cnt++] = i - 5;
    if (i % 5 != 0)                          n[cnt++] = i - 1;
    if ((i + 1) % 5 != 0)                    n[cnt++] = i + 1;
    if (i + 5 < 25)                          n[cnt++] = i + 5;
    if (i - 6 >= 0 && i % 5 != 0)            n[cnt++] = i - 6;
    if (i - 4 >= 0 && (i + 1) % 5 != 0)      n[cnt++] = i - 4;
    if (i + 4 < 25 && i % 5 != 0)            n[cnt++] = i + 4;
    if (i + 6 < 25 && (i + 1) % 5 != 0)      n[cnt++] = i + 6;
    while (cnt < 8) n[cnt++] = -1;
    return n[j];
}

// ---------------------------------------------------------------------------
// Fused per-node MLP: X[64,K] -> tanh(X@Wa + ba)[64,600] -> softmax(h@Wb + bb)
// Block = (batch tile of 64, node). 256 threads = 16 bgrp x 16 hgrp, 4x4 tiles.
// Hidden processed in chunks of 64 (600 padded to 640 with zero guards).
// STAGE2: first 80 inputs gathered from stage-1 preds of neighbors.
// ---------------------------------------------------------------------------
template<int KDIM, bool STAGE2>
__launch_bounds__(256)
__global__ void mlp_kernel(const float* __restrict__ feat,   // [25][B][256]
                           const float* __restrict__ preds,  // [25][B][10]
                           const float* __restrict__ Wa,     // [25][336][600]
                           const float* __restrict__ ba,     // [25][600]
                           const float* __restrict__ Wb,     // [25][600][10]
                           const float* __restrict__ bb,     // [25][10]
                           float* __restrict__ outp,         // [25][B][10]
                           int B)
{
    __shared__ __align__(16) float Xs[8][64];
    __shared__ __align__(16) float Was[8][64];
    __shared__ float Hcs[64][65];
    __shared__ float Wbs[64][10];
    __shared__ float lg[64][12];
    __shared__ int s_nei[8];

    const int n   = blockIdx.y;
    const int b0  = blockIdx.x * 64;
    const int tid = threadIdx.x;
    const int bgrp = tid & 15;
    const int hgrp = tid >> 4;

    if (tid < 8) s_nei[tid] = nei_of(n, tid);
    for (int idx = tid; idx < 640; idx += 256)
        lg[idx / 10][idx % 10] = bb[n * 10 + idx % 10];

    const float* Wan   = Wa + (size_t)n * 336 * 600 + (size_t)(STAGE2 ? 0 : 80) * 600;
    const float* ban   = ba + n * 600;
    const float* Wbn   = Wb + (size_t)n * 600 * 10;
    const float* featn = feat + (size_t)n * B * 256;

    for (int hc = 0; hc < 640; hc += 64) {
        float acc[4][4];
        #pragma unroll
        for (int j = 0; j < 4; j++) {
            int h = hc + hgrp * 4 + j;
            float bv = (h < 600) ? ban[h] : 0.f;
            #pragma unroll
            for (int i = 0; i < 4; i++) acc[i][j] = bv;
        }

        for (int k0 = 0; k0 < KDIM; k0 += 8) {
            __syncthreads();
            // Xs[kj][bi] = X[b0+bi][k0+kj]
            #pragma unroll
            for (int t = 0; t < 2; t++) {
                int e = tid * 2 + t;
                int bi = e >> 3, kj = e & 7;
                int k = k0 + kj;
                float v;
                if (STAGE2 && k < 80) {
                    int jn = k / 10, c = k - jn * 10;
                    int ne = s_nei[jn];
                    v = (ne >= 0) ? preds[((size_t)ne * B + b0 + bi) * 10 + c] : 0.f;
                } else {
                    int ch = STAGE2 ? (k - 80) : k;
                    v = featn[((size_t)(b0 + bi)) * 256 + ch];
                }
                Xs[kj][bi] = v;
            }
            // Was[kj][hi] = Wa[n][koff+k0+kj][hc+hi]
            #pragma unroll
            for (int t = 0; t < 2; t++) {
                int e = tid * 2 + t;
                int kj = e >> 6, hi = e & 63;
                int h = hc + hi;
                Was[kj][hi] = (h < 600) ? Wan[(size_t)(k0 + kj) * 600 + h] : 0.f;
            }
            __syncthreads();

            #pragma unroll
            for (int kj = 0; kj < 8; kj++) {
                float4 xv = *reinterpret_cast<const float4*>(&Xs[kj][bgrp * 4]);
                float4 wv = *reinterpret_cast<const float4*>(&Was[kj][hgrp * 4]);
                float xb[4] = {xv.x, xv.y, xv.z, xv.w};
                float wh[4] = {wv.x, wv.y, wv.z, wv.w};
                #pragma unroll
                for (int i = 0; i < 4; i++)
                    #pragma unroll
                    for (int j = 0; j < 4; j++)
                        acc[i][j] = fmaf(xb[i], wh[j], acc[i][j]);
            }
        }

        // tanh + stage hidden chunk
        #pragma unroll
        for (int i = 0; i < 4; i++)
            #pragma unroll
            for (int j = 0; j < 4; j++)
                Hcs[bgrp * 4 + i][hgrp * 4 + j] = tanhf(acc[i][j]);

        for (int idx = tid; idx < 640; idx += 256) {
            int hi = idx / 10, c = idx % 10;
            int h = hc + hi;
            Wbs[hi][c] = (h < 600) ? Wbn[(size_t)h * 10 + c] : 0.f;
        }
        __syncthreads();

        if (tid < 128) {
            int bq = tid >> 1, c0 = (tid & 1) * 5;
            #pragma unroll
            for (int c = 0; c < 5; c++) {
                float s = 0.f;
                #pragma unroll 8
                for (int hj = 0; hj < 64; hj++)
                    s = fmaf(Hcs[bq][hj], Wbs[hj][c0 + c], s);
                lg[bq][c0 + c] += s;
            }
        }
    }
    __syncthreads();

    if (tid < 64) {
        float l[10];
        #pragma unroll
        for (int c = 0; c < 10; c++) l[c] = lg[tid][c];
        float m = l[0];
        #pragma unroll
        for (int c = 1; c < 10; c++) m = fmaxf(m, l[c]);
        float e[10]; float s = 0.f;
        #pragma unroll
        for (int c = 0; c < 10; c++) { e[c] = expf(l[c] - m); s += e[c]; }
        float inv = 1.f / s;
        size_t base = ((size_t)n * B + b0 + tid) * 10;
        #pragma unroll
        for (int c = 0; c < 10; c++) outp[base + c] = e[c] * inv;
    }
}

// ---------------------------------------------------------------------------
// mean over 25 nodes: out_mean[b][c] = mean_n second[n][b][c]
// ---------------------------------------------------------------------------
__global__ void mean_kernel(const float* __restrict__ second, float* __restrict__ outm, int B)
{
    int idx = blockIdx.x * blockDim.x + threadIdx.x;
    if (idx >= B * 10) return;
    float s = 0.f;
    #pragma unroll
    for (int n = 0; n < 25; n++) s += second[(size_t)n * B * 10 + idx];
    outm[idx] = s * (1.f / 25.f);
}

// ---------------------------------------------------------------------------
// Host launcher
// ---------------------------------------------------------------------------
extern "C" void kernel_launch(void* const* d_in, const int* in_sizes, int n_in,
                              void* d_out, int out_size)
{
    const float* x  = (const float*)d_in[0];
    const float* W1 = (const float*)d_in[1];
    const float* b1 = (const float*)d_in[2];
    const float* g1 = (const float*)d_in[3];
    const float* be1= (const float*)d_in[4];
    const float* m1 = (const float*)d_in[5];
    const float* v1 = (const float*)d_in[6];
    const float* W2 = (const float*)d_in[7];
    const float* b2 = (const float*)d_in[8];
    const float* g2 = (const float*)d_in[9];
    const float* be2= (const float*)d_in[10];
    const float* m2 = (const float*)d_in[11];
    const float* v2 = (const float*)d_in[12];
    const float* W3 = (const float*)d_in[13];
    const float* b3 = (const float*)d_in[14];
    const float* g3 = (const float*)d_in[15];
    const float* be3= (const float*)d_in[16];
    const float* m3 = (const float*)d_in[17];
    const float* v3 = (const float*)d_in[18];
    const float* W4 = (const float*)d_in[19];
    const float* b4 = (const float*)d_in[20];
    const float* g4 = (const float*)d_in[21];
    const float* be4= (const float*)d_in[22];
    const float* m4 = (const float*)d_in[23];
    const float* v4 = (const float*)d_in[24];
    const float* Wa = (const float*)d_in[25];
    const float* ba = (const float*)d_in[26];
    const float* Wb = (const float*)d_in[27];
    const float* bb = (const float*)d_in[28];

    const int B = in_sizes[0] / (3 * 20 * 20);

    float *conv1b, *pool1b, *conv2b, *pool2b, *conv3b, *featb, *predsb, *scaleb, *biasb;
    cudaGetSymbolAddress((void**)&conv1b, g_conv1);
    cudaGetSymbolAddress((void**)&pool1b, g_pool1);
    cudaGetSymbolAddress((void**)&conv2b, g_conv2);
    cudaGetSymbolAddress((void**)&pool2b, g_pool2);
    cudaGetSymbolAddress((void**)&conv3b, g_conv3);
    cudaGetSymbolAddress((void**)&featb,  g_feat);
    cudaGetSymbolAddress((void**)&predsb, g_preds);
    cudaGetSymbolAddress((void**)&scaleb, g_scale);
    cudaGetSymbolAddress((void**)&biasb,  g_bias);

    // shared-memory sizes
    const int smem1 = (3 * 49 + 64 * 27) * 4;     // 7.3 KB
    const int smem2 = (8 * 49 + 128 * 73) * 4;    // 38.0 KB
    const int smem3 = (8 * 49 + 256 * 73) * 4;    // 74.5 KB
    cudaFuncSetAttribute(conv_bn_relu_kernel<3, 64, 3, 20, 64, false>,
                         cudaFuncAttributeMaxDynamicSharedMemorySize, smem1);
    cudaFuncSetAttribute(conv_bn_relu_kernel<64, 128, 8, 10, 128, false>,
                         cudaFuncAttributeMaxDynamicSharedMemorySize, smem2);
    cudaFuncSetAttribute(conv_bn_relu_kernel<128, 256, 8, 5, 256, false>,
                         cudaFuncAttributeMaxDynamicSharedMemorySize, smem3);
    cudaFuncSetAttribute(conv_bn_relu_kernel<256, 256, 8, 5, 256, true>,
                         cudaFuncAttributeMaxDynamicSharedMemorySize, smem3);

    // BN folding
    bn_prep<<<1, 64>>> (b1, g1, be1, m1, v1, 64, 0);
    bn_prep<<<1, 128>>>(b2, g2, be2, m2, v2, 128, 64);
    bn_prep<<<1, 256>>>(b3, g3, be3, m3, v3, 256, 192);
    bn_prep<<<1, 256>>>(b4, g4, be4, m4, v4, 256, 448);

    // conv1: [B,3,20,20] -> [B,64,20,20]
    conv_bn_relu_kernel<3, 64, 3, 20, 64, false>
        <<<dim3(16, B), 64, smem1>>>(x, W1, scaleb + 0, biasb + 0, conv1b, B);
    // pool1 -> [B,64,10,10]
    {
        size_t total = (size_t)B * 64 * 100;
        maxpool_kernel<<<(unsigned)((total + 255) / 256), 256>>>(conv1b, pool1b, B, 64, 20);
    }
    // conv2: -> [B,128,10,10]
    conv_bn_relu_kernel<64, 128, 8, 10, 128, false>
        <<<dim3(4, B), 128, smem2>>>(pool1b, W2, scaleb + 64, biasb + 64, conv2b, B);
    // pool2 -> [B,128,5,5]
    {
        size_t total = (size_t)B * 128 * 25;
        maxpool_kernel<<<(unsigned)((total + 255) / 256), 256>>>(conv2b, pool2b, B, 128, 10);
    }
    // conv3: -> [B,256,5,5]
    conv_bn_relu_kernel<128, 256, 8, 5, 256, false>
        <<<dim3(1, B), 256, smem3>>>(pool2b, W3, scaleb + 192, biasb + 192, conv3b, B);
    // conv4: -> feats [25,B,256]
    conv_bn_relu_kernel<256, 256, 8, 5, 256, true>
        <<<dim3(1, B), 256, smem3>>>(conv3b, W4, scaleb + 448, biasb + 448, featb, B);

    float* out   = (float*)d_out;
    float* secnd = out + (size_t)B * 10;

    // stage 1: K = 256 (zeros block skipped, Wa rows 80:336)
    mlp_kernel<256, false><<<dim3(B / 64, 25), 256>>>(featb, predsb, Wa, ba, Wb, bb, predsb, B);
    // stage 2: K = 336 (80 neighbor-pred dims + 256 feats)
    mlp_kernel<336, true><<<dim3(B / 64, 25), 256>>>(featb, predsb, Wa, ba, Wb, bb, secnd, B);
    // mean over nodes
    mean_kernel<<<(B * 10 + 255) / 256, 256>>>(secnd, out, B);
}